// round 1
// baseline (speedup 1.0000x reference)
#include <cuda_runtime.h>
#include <math.h>

// Problem constants
#define BB   8
#define SS   2048
#define HH   256
#define NHH  4
#define HDD  64
#define MTOT (BB * SS)   // 16384

// ---------------------------------------------------------------------------
// Device scratch (no allocations allowed; __device__ globals are the rule-safe
// scratch mechanism). ~84 MB total.
// ---------------------------------------------------------------------------
__device__ float g_Q[BB * NHH * SS * HDD];   // [b*NH+h][s][d]
__device__ float g_K[BB * NHH * SS * HDD];
__device__ float g_V[BB * NHH * SS * HDD];
__device__ float g_ctx[MTOT * HH];           // [b][s][h*64+d] merged heads
__device__ float g_resid[MTOT * HH];         // out-proj + residual, pre-LN

// ---------------------------------------------------------------------------
// Kernel 1: fused QKV projection.  C = X @ W + b, written split-head.
// Grid: (H/64=4 n-tiles, M/64=256 m-tiles, 3 matrices). Block 256 threads.
// BM=BN=64, BK=16, 4x4 per thread.
// ---------------------------------------------------------------------------
__global__ __launch_bounds__(256) void qkv_kernel(
    const float* __restrict__ X,
    const float* __restrict__ Wq, const float* __restrict__ bq,
    const float* __restrict__ Wk, const float* __restrict__ bk,
    const float* __restrict__ Wv, const float* __restrict__ bv)
{
    __shared__ float As[16][65];   // transposed X tile: As[k][m]
    __shared__ float Bs[16][64];   // W tile: Bs[k][n]

    const float* W; const float* bias; float* out;
    if (blockIdx.z == 0)      { W = Wq; bias = bq; out = g_Q; }
    else if (blockIdx.z == 1) { W = Wk; bias = bk; out = g_K; }
    else                      { W = Wv; bias = bv; out = g_V; }

    const int t  = threadIdx.x;
    const int tx = t & 15;         // n sub-tile
    const int ty = t >> 4;         // m sub-tile
    const int m0 = blockIdx.y * 64;
    const int n0 = blockIdx.x * 64;

    const int lr = t >> 2;         // X load: row 0..63
    const int lk = (t & 3) << 2;   // X load: k offset 0,4,8,12
    const int wr = t >> 4;         // W load: k row 0..15
    const int wc = (t & 15) << 2;  // W load: n col 0..60

    float acc[4][4] = {};

    for (int k0 = 0; k0 < HH; k0 += 16) {
        float4 xv = *(const float4*)(X + (m0 + lr) * HH + (k0 + lk));
        float4 wv = *(const float4*)(W + (k0 + wr) * HH + (n0 + wc));
        As[lk + 0][lr] = xv.x;
        As[lk + 1][lr] = xv.y;
        As[lk + 2][lr] = xv.z;
        As[lk + 3][lr] = xv.w;
        *(float4*)&Bs[wr][wc] = wv;
        __syncthreads();
        #pragma unroll
        for (int k = 0; k < 16; k++) {
            float a[4];
            #pragma unroll
            for (int ii = 0; ii < 4; ii++) a[ii] = As[k][ty * 4 + ii];
            float4 b4 = *(float4*)&Bs[k][tx * 4];
            float br[4] = {b4.x, b4.y, b4.z, b4.w};
            #pragma unroll
            for (int ii = 0; ii < 4; ii++)
                #pragma unroll
                for (int jj = 0; jj < 4; jj++)
                    acc[ii][jj] += a[ii] * br[jj];
        }
        __syncthreads();
    }

    // Epilogue: + bias, store split-head [b*NH+h][s][d]. One head per block (BN==64).
    const int head = blockIdx.x;
    float4 bb = *(const float4*)(bias + n0 + tx * 4);
    #pragma unroll
    for (int ii = 0; ii < 4; ii++) {
        int m  = m0 + ty * 4 + ii;
        int b_ = m >> 11;            // /2048
        int s_ = m & (SS - 1);
        float4 o;
        o.x = acc[ii][0] + bb.x;
        o.y = acc[ii][1] + bb.y;
        o.z = acc[ii][2] + bb.z;
        o.w = acc[ii][3] + bb.w;
        *(float4*)(out + ((b_ * NHH + head) * SS + s_) * HDD + tx * 4) = o;
    }
}

// ---------------------------------------------------------------------------
// Kernel 2: flash attention (fp32, online softmax), BQ=64, BK=32.
// Grid: (S/64=32 q-blocks, B*NH=32 bh). Block 256 threads.
// Thread (ri = t/16 in 0..15, ci = t%16): owns rows 4ri..4ri+3.
//   score phase : k-cols {ci, ci+16}          -> s[4][2]
//   PV phase    : output dims {4ci..4ci+3}    -> acc[4][4]
// Static smem: Qs 64x68 + Ks 32x68 + Vs 32x68 + Ps 64x36 = 44,032 B (<48K).
// ---------------------------------------------------------------------------
__global__ __launch_bounds__(256) void attn_kernel(const float* __restrict__ mask)
{
    __shared__ float Qs[64][68];
    __shared__ float Ks[32][68];
    __shared__ float Vs[32][68];
    __shared__ float Ps[64][36];

    const int t  = threadIdx.x;
    const int ci = t & 15;
    const int ri = t >> 4;
    const int qb = blockIdx.x;          // 0..31
    const int bh = blockIdx.y;          // 0..31
    const int b_ = bh >> 2;
    const int h_ = bh & 3;

    const float* Qg = g_Q + bh * SS * HDD;
    const float* Kg = g_K + bh * SS * HDD;
    const float* Vg = g_V + bh * SS * HDD;
    const float* Mg = mask + b_ * SS * SS;

    // Load Q tile (64x64) -> Qs
    {
        int idx = t * 4;
        #pragma unroll
        for (int it = 0; it < 4; it++) {
            int row = idx >> 6, d = idx & 63;
            *(float4*)&Qs[row][d] =
                *(const float4*)(Qg + (qb * 64 + row) * HDD + d);
            idx += 1024;
        }
    }

    float m_run[4], l_run[4], acc[4][4];
    #pragma unroll
    for (int ii = 0; ii < 4; ii++) {
        m_run[ii] = -1e30f;
        l_run[ii] = 0.0f;
        #pragma unroll
        for (int jj = 0; jj < 4; jj++) acc[ii][jj] = 0.0f;
    }

    const float scale = 0.125f;  // 1/sqrt(64)

    for (int kt = 0; kt < SS / 32; kt++) {
        __syncthreads();  // previous iter's PV reads of Ks/Vs/Ps done; Q load done (kt==0)

        // Load K,V tiles (32x64 each): 2 float4 per thread per tile
        {
            int idx = t * 4;
            #pragma unroll
            for (int it = 0; it < 2; it++) {
                int row = idx >> 6, d = idx & 63;
                *(float4*)&Ks[row][d] =
                    *(const float4*)(Kg + (kt * 32 + row) * HDD + d);
                *(float4*)&Vs[row][d] =
                    *(const float4*)(Vg + (kt * 32 + row) * HDD + d);
                idx += 1024;
            }
        }
        __syncthreads();

        // ---- scores: s[ii][jj] = Q[row] . K[kcol], kcol = ci + 16*jj ----
        float s[4][2] = {};
        #pragma unroll 8
        for (int d = 0; d < 64; d++) {
            float k0v = Ks[ci][d];
            float k1v = Ks[ci + 16][d];
            #pragma unroll
            for (int ii = 0; ii < 4; ii++) {
                float q = Qs[ri * 4 + ii][d];
                s[ii][0] += q * k0v;
                s[ii][1] += q * k1v;
            }
        }

        // ---- mask + online softmax (per row, reduce across 16 lanes) ----
        #pragma unroll
        for (int ii = 0; ii < 4; ii++) {
            int qrow = qb * 64 + ri * 4 + ii;
            const float* mrow = Mg + qrow * SS + kt * 32;
            float s0 = s[ii][0] * scale + mrow[ci];
            float s1 = s[ii][1] * scale + mrow[ci + 16];
            float mx = fmaxf(s0, s1);
            #pragma unroll
            for (int off = 8; off; off >>= 1)
                mx = fmaxf(mx, __shfl_xor_sync(0xffffffffu, mx, off));
            float mn = fmaxf(m_run[ii], mx);
            float p0 = __expf(s0 - mn);
            float p1 = __expf(s1 - mn);
            float ts = p0 + p1;
            #pragma unroll
            for (int off = 8; off; off >>= 1)
                ts += __shfl_xor_sync(0xffffffffu, ts, off);
            float corr = __expf(m_run[ii] - mn);
            m_run[ii] = mn;
            l_run[ii] = l_run[ii] * corr + ts;
            #pragma unroll
            for (int jj = 0; jj < 4; jj++) acc[ii][jj] *= corr;
            Ps[ri * 4 + ii][ci]      = p0;
            Ps[ri * 4 + ii][ci + 16] = p1;
        }
        __syncthreads();

        // ---- PV: acc[ii][jj] += sum_kk P[row][kk] * V[kk][4ci+jj] ----
        #pragma unroll 4
        for (int kk = 0; kk < 32; kk++) {
            float v0 = Vs[kk][ci * 4 + 0];
            float v1 = Vs[kk][ci * 4 + 1];
            float v2 = Vs[kk][ci * 4 + 2];
            float v3 = Vs[kk][ci * 4 + 3];
            #pragma unroll
            for (int ii = 0; ii < 4; ii++) {
                float p = Ps[ri * 4 + ii][kk];
                acc[ii][0] += p * v0;
                acc[ii][1] += p * v1;
                acc[ii][2] += p * v2;
                acc[ii][3] += p * v3;
            }
        }
    }

    // ---- finalize: divide by l, write merged-head ctx [b][s][h*64+d] ----
    #pragma unroll
    for (int ii = 0; ii < 4; ii++) {
        float inv = 1.0f / l_run[ii];
        int srow = qb * 64 + ri * 4 + ii;
        float4 o;
        o.x = acc[ii][0] * inv;
        o.y = acc[ii][1] * inv;
        o.z = acc[ii][2] * inv;
        o.w = acc[ii][3] * inv;
        *(float4*)(g_ctx + (b_ * SS + srow) * HH + h_ * HDD + ci * 4) = o;
    }
}

// ---------------------------------------------------------------------------
// Kernel 3: output projection + residual.  resid = ctx @ Wo + bo + X.
// Same SGEMM structure as kernel 1; natural [m][n] output layout.
// ---------------------------------------------------------------------------
__global__ __launch_bounds__(256) void proj_kernel(
    const float* __restrict__ X,
    const float* __restrict__ Wo, const float* __restrict__ bo)
{
    __shared__ float As[16][65];
    __shared__ float Bs[16][64];

    const int t  = threadIdx.x;
    const int tx = t & 15;
    const int ty = t >> 4;
    const int m0 = blockIdx.y * 64;
    const int n0 = blockIdx.x * 64;

    const int lr = t >> 2;
    const int lk = (t & 3) << 2;
    const int wr = t >> 4;
    const int wc = (t & 15) << 2;

    float acc[4][4] = {};

    for (int k0 = 0; k0 < HH; k0 += 16) {
        float4 xv = *(const float4*)(g_ctx + (m0 + lr) * HH + (k0 + lk));
        float4 wv = *(const float4*)(Wo + (k0 + wr) * HH + (n0 + wc));
        As[lk + 0][lr] = xv.x;
        As[lk + 1][lr] = xv.y;
        As[lk + 2][lr] = xv.z;
        As[lk + 3][lr] = xv.w;
        *(float4*)&Bs[wr][wc] = wv;
        __syncthreads();
        #pragma unroll
        for (int k = 0; k < 16; k++) {
            float a[4];
            #pragma unroll
            for (int ii = 0; ii < 4; ii++) a[ii] = As[k][ty * 4 + ii];
            float4 b4 = *(float4*)&Bs[k][tx * 4];
            float br[4] = {b4.x, b4.y, b4.z, b4.w};
            #pragma unroll
            for (int ii = 0; ii < 4; ii++)
                #pragma unroll
                for (int jj = 0; jj < 4; jj++)
                    acc[ii][jj] += a[ii] * br[jj];
        }
        __syncthreads();
    }

    float4 bb = *(const float4*)(bo + n0 + tx * 4);
    #pragma unroll
    for (int ii = 0; ii < 4; ii++) {
        int m = m0 + ty * 4 + ii;
        float4 xr = *(const float4*)(X + m * HH + n0 + tx * 4);
        float4 o;
        o.x = acc[ii][0] + bb.x + xr.x;
        o.y = acc[ii][1] + bb.y + xr.y;
        o.z = acc[ii][2] + bb.z + xr.z;
        o.w = acc[ii][3] + bb.w + xr.w;
        *(float4*)(g_resid + m * HH + n0 + tx * 4) = o;
    }
}

// ---------------------------------------------------------------------------
// Kernel 4: LayerNorm over H=256. One row per warp (8 floats/lane), exact
// two-pass (mean, then mean((x-mu)^2)) matching the reference.
// ---------------------------------------------------------------------------
__global__ __launch_bounds__(256) void ln_kernel(
    const float* __restrict__ gamma, const float* __restrict__ beta,
    float* __restrict__ out)
{
    const int lane = threadIdx.x & 31;
    const int warp = threadIdx.x >> 5;
    const int row  = blockIdx.x * 8 + warp;

    const float* r = g_resid + row * HH + lane * 8;
    float4 a  = *(const float4*)(r);
    float4 b4 = *(const float4*)(r + 4);

    float sum = a.x + a.y + a.z + a.w + b4.x + b4.y + b4.z + b4.w;
    #pragma unroll
    for (int off = 16; off; off >>= 1)
        sum += __shfl_xor_sync(0xffffffffu, sum, off);
    float mu = sum * (1.0f / 256.0f);

    float d0 = a.x - mu, d1 = a.y - mu, d2 = a.z - mu, d3 = a.w - mu;
    float d4 = b4.x - mu, d5 = b4.y - mu, d6 = b4.z - mu, d7 = b4.w - mu;
    float vs = d0 * d0 + d1 * d1 + d2 * d2 + d3 * d3
             + d4 * d4 + d5 * d5 + d6 * d6 + d7 * d7;
    #pragma unroll
    for (int off = 16; off; off >>= 1)
        vs += __shfl_xor_sync(0xffffffffu, vs, off);
    float inv = rsqrtf(vs * (1.0f / 256.0f) + 1e-12f);

    float4 g0 = *(const float4*)(gamma + lane * 8);
    float4 g1 = *(const float4*)(gamma + lane * 8 + 4);
    float4 e0 = *(const float4*)(beta + lane * 8);
    float4 e1 = *(const float4*)(beta + lane * 8 + 4);

    float4 o0, o1;
    o0.x = d0 * inv * g0.x + e0.x;
    o0.y = d1 * inv * g0.y + e0.y;
    o0.z = d2 * inv * g0.z + e0.z;
    o0.w = d3 * inv * g0.w + e0.w;
    o1.x = d4 * inv * g1.x + e1.x;
    o1.y = d5 * inv * g1.y + e1.y;
    o1.z = d6 * inv * g1.z + e1.z;
    o1.w = d7 * inv * g1.w + e1.w;

    float* op = out + row * HH + lane * 8;
    *(float4*)(op)     = o0;
    *(float4*)(op + 4) = o1;
}

// ---------------------------------------------------------------------------
extern "C" void kernel_launch(void* const* d_in, const int* in_sizes, int n_in,
                              void* d_out, int out_size)
{
    const float* X     = (const float*)d_in[0];
    const float* mask  = (const float*)d_in[1];
    const float* Wq    = (const float*)d_in[2];
    const float* bq    = (const float*)d_in[3];
    const float* Wk    = (const float*)d_in[4];
    const float* bk    = (const float*)d_in[5];
    const float* Wv    = (const float*)d_in[6];
    const float* bv    = (const float*)d_in[7];
    const float* Wo    = (const float*)d_in[8];
    const float* bo    = (const float*)d_in[9];
    const float* gamma = (const float*)d_in[10];
    const float* beta  = (const float*)d_in[11];
    float* out = (float*)d_out;

    qkv_kernel<<<dim3(HH / 64, MTOT / 64, 3), 256>>>(X, Wq, bq, Wk, bk, Wv, bv);
    attn_kernel<<<dim3(SS / 64, BB * NHH), 256>>>(mask);
    proj_kernel<<<dim3(HH / 64, MTOT / 64), 256>>>(X, Wo, bo);
    ln_kernel<<<MTOT / 8, 256>>>(gamma, beta, out);
}

// round 2
// speedup vs baseline: 4.6398x; 4.6398x over previous
#include <cuda_runtime.h>
#include <cuda_bf16.h>
#include <stdint.h>
#include <math.h>

#define BB   8
#define SS   2048
#define HH   256
#define NHH  4
#define HDD  64
#define MTOT (BB * SS)   // 16384

// ---------------------------------------------------------------------------
// Scratch (__device__ globals only; no allocations allowed).
// ---------------------------------------------------------------------------
__device__ __align__(128) __nv_bfloat16 g_Qb[32 * SS * HDD];   // [bh][s][d]
__device__ __align__(128) __nv_bfloat16 g_Kb[32 * SS * HDD];   // [bh][s][d]
__device__ __align__(128) __nv_bfloat16 g_Vt[32 * HDD * SS];   // [bh][d][s] (transposed)
__device__ __align__(128) __nv_bfloat16 g_ctxb[MTOT * HH];     // [m][h*64+d]
__device__ __align__(128) float         g_resid[MTOT * HH];

// ---------------------------------------------------------------------------
// Helpers
// ---------------------------------------------------------------------------
__device__ __forceinline__ uint32_t packbf(float lo, float hi) {
    uint32_t r;
    asm("cvt.rn.bf16x2.f32 %0, %1, %2;" : "=r"(r) : "f"(hi), "f"(lo));
    return r;
}

// D = A(16x16 bf16,row) @ B(16x8 bf16,col) + C, fp32 accum
__device__ __forceinline__ void mma16816(float* c, const uint32_t* a, const uint32_t* b) {
    asm volatile(
        "mma.sync.aligned.m16n8k16.row.col.f32.bf16.bf16.f32 "
        "{%0,%1,%2,%3}, {%4,%5,%6,%7}, {%8,%9}, {%0,%1,%2,%3};\n"
        : "+f"(c[0]), "+f"(c[1]), "+f"(c[2]), "+f"(c[3])
        : "r"(a[0]), "r"(a[1]), "r"(a[2]), "r"(a[3]), "r"(b[0]), "r"(b[1]));
}

#define GP 40   // smem pitch (bf16) for GEMM tiles
#define KP 72   // smem pitch (bf16) for attn K / Vt tiles

// ---------------------------------------------------------------------------
// Kernel 1: QKV projection, bf16 mma.  BM=128 BN=64 BK=32, 4 warps.
// Writes Q,K split-head bf16 [bh][s][d]; V transposed bf16 [bh][d][s].
// ---------------------------------------------------------------------------
__global__ __launch_bounds__(128) void qkv_kernel(
    const float* __restrict__ X,
    const float* __restrict__ Wq, const float* __restrict__ bq,
    const float* __restrict__ Wk, const float* __restrict__ bk,
    const float* __restrict__ Wv, const float* __restrict__ bv)
{
    __shared__ __nv_bfloat16 As[128 * GP];
    __shared__ __nv_bfloat16 Bs[64 * GP];

    const int z = blockIdx.z;
    const float* W;  const float* bias;
    if (z == 0)      { W = Wq; bias = bq; }
    else if (z == 1) { W = Wk; bias = bk; }
    else             { W = Wv; bias = bv; }

    const int t = threadIdx.x;
    const int w = t >> 5, lane = t & 31;
    const int g = lane >> 2, tig = lane & 3;
    const int m0 = blockIdx.y * 128, n0 = blockIdx.x * 64;

    float c[2][8][4];
    #pragma unroll
    for (int mt = 0; mt < 2; mt++)
        #pragma unroll
        for (int j = 0; j < 8; j++)
            #pragma unroll
            for (int i = 0; i < 4; i++) c[mt][j][i] = 0.0f;

    for (int k0 = 0; k0 < HH; k0 += 32) {
        // X tile 128x32 fp32 -> As bf16 [m][k]
        #pragma unroll
        for (int i = 0; i < 8; i++) {
            int m = (t >> 3) + 16 * i;
            int k = 4 * (t & 7);
            float4 v = *(const float4*)(X + (m0 + m) * HH + k0 + k);
            uint2 p;
            p.x = packbf(v.x, v.y);
            p.y = packbf(v.z, v.w);
            *(uint2*)&As[m * GP + k] = p;
        }
        // W tile 32x64 fp32 -> Bs bf16 transposed [n][k]
        #pragma unroll
        for (int i = 0; i < 8; i++) {
            int idx = 2 * t + 256 * i;
            int k = idx >> 6, n = idx & 63;
            float2 v = *(const float2*)(W + (k0 + k) * HH + n0 + n);
            Bs[n * GP + k]       = __float2bfloat16(v.x);
            Bs[(n + 1) * GP + k] = __float2bfloat16(v.y);
        }
        __syncthreads();

        uint32_t a[2][2][4];
        #pragma unroll
        for (int mt = 0; mt < 2; mt++)
            #pragma unroll
            for (int kt = 0; kt < 2; kt++) {
                int r = w * 32 + mt * 16;
                a[mt][kt][0] = *(const uint32_t*)&As[(r + g)     * GP + kt * 16 + 2 * tig];
                a[mt][kt][1] = *(const uint32_t*)&As[(r + g + 8) * GP + kt * 16 + 2 * tig];
                a[mt][kt][2] = *(const uint32_t*)&As[(r + g)     * GP + kt * 16 + 2 * tig + 8];
                a[mt][kt][3] = *(const uint32_t*)&As[(r + g + 8) * GP + kt * 16 + 2 * tig + 8];
            }
        #pragma unroll
        for (int j = 0; j < 8; j++) {
            #pragma unroll
            for (int kt = 0; kt < 2; kt++) {
                uint32_t b[2];
                b[0] = *(const uint32_t*)&Bs[(8 * j + g) * GP + kt * 16 + 2 * tig];
                b[1] = *(const uint32_t*)&Bs[(8 * j + g) * GP + kt * 16 + 2 * tig + 8];
                mma16816(c[0][j], a[0][kt], b);
                mma16816(c[1][j], a[1][kt], b);
            }
        }
        __syncthreads();
    }

    // Epilogue: +bias, write split-head
    const int head = blockIdx.x;   // BN==64 => one head per n-block
    #pragma unroll
    for (int mt = 0; mt < 2; mt++) {
        int r0 = m0 + w * 32 + mt * 16 + g;
        #pragma unroll
        for (int half = 0; half < 2; half++) {
            int m  = r0 + half * 8;
            int b_ = m >> 11;
            int s_ = m & (SS - 1);
            int bh = b_ * NHH + head;
            #pragma unroll
            for (int j = 0; j < 8; j++) {
                int d = 8 * j + 2 * tig;
                float v0 = c[mt][j][half * 2 + 0] + bias[n0 + d];
                float v1 = c[mt][j][half * 2 + 1] + bias[n0 + d + 1];
                if (z == 0) {
                    *(uint32_t*)&g_Qb[(bh * SS + s_) * HDD + d] = packbf(v0, v1);
                } else if (z == 1) {
                    *(uint32_t*)&g_Kb[(bh * SS + s_) * HDD + d] = packbf(v0, v1);
                } else {
                    g_Vt[(bh * HDD + d)     * SS + s_] = __float2bfloat16(v0);
                    g_Vt[(bh * HDD + d + 1) * SS + s_] = __float2bfloat16(v1);
                }
            }
        }
    }
}

// ---------------------------------------------------------------------------
// Kernel 2: flash attention, bf16 mma, BQ=64, BK=64, 4 warps.
// ---------------------------------------------------------------------------
__global__ __launch_bounds__(128) void attn_kernel(const float* __restrict__ mask)
{
    __shared__ __nv_bfloat16 Ks[64 * KP];   // [kv][d]
    __shared__ __nv_bfloat16 Vs[64 * KP];   // [d][kv]

    const int t = threadIdx.x;
    const int w = t >> 5, lane = t & 31;
    const int g = lane >> 2, tig = lane & 3;
    const int bh = blockIdx.x;             // x = bh: heads of same batch share mask in-wave
    const int qb = blockIdx.y;
    const int b_ = bh >> 2;
    const int h_ = bh & 3;

    const __nv_bfloat16* Qg = g_Qb + bh * SS * HDD;
    const __nv_bfloat16* Kg = g_Kb + bh * SS * HDD;
    const __nv_bfloat16* Vg = g_Vt + bh * HDD * SS;
    const float* Mg = mask + (size_t)b_ * SS * SS;

    const int qrow0 = qb * 64 + w * 16 + g;
    const int qrow1 = qrow0 + 8;

    // Q A-fragments, resident for the whole loop
    uint32_t aq[4][4];
    {
        const __nv_bfloat16* r0 = Qg + qrow0 * HDD;
        const __nv_bfloat16* r1 = Qg + qrow1 * HDD;
        #pragma unroll
        for (int kt = 0; kt < 4; kt++) {
            aq[kt][0] = *(const uint32_t*)(r0 + kt * 16 + 2 * tig);
            aq[kt][1] = *(const uint32_t*)(r1 + kt * 16 + 2 * tig);
            aq[kt][2] = *(const uint32_t*)(r0 + kt * 16 + 2 * tig + 8);
            aq[kt][3] = *(const uint32_t*)(r1 + kt * 16 + 2 * tig + 8);
        }
    }

    float o[8][4];
    #pragma unroll
    for (int jo = 0; jo < 8; jo++)
        #pragma unroll
        for (int i = 0; i < 4; i++) o[jo][i] = 0.0f;
    float m_run0 = -1e30f, m_run1 = -1e30f, l_run0 = 0.0f, l_run1 = 0.0f;
    const float scale = 0.125f;   // 1/sqrt(64)

    for (int kv0 = 0; kv0 < SS; kv0 += 64) {
        __syncthreads();
        // Load K tile [kv][d] and Vt tile [d][kv] (each 64x64 bf16)
        {
            int row = t >> 1, half = t & 1;
            const uint4* ks = (const uint4*)(Kg + (kv0 + row) * HDD + half * 32);
            uint4* kd = (uint4*)&Ks[row * KP + half * 32];
            kd[0] = ks[0]; kd[1] = ks[1]; kd[2] = ks[2]; kd[3] = ks[3];
            const uint4* vs = (const uint4*)(Vg + row * SS + kv0 + half * 32);
            uint4* vd = (uint4*)&Vs[row * KP + half * 32];
            vd[0] = vs[0]; vd[1] = vs[1]; vd[2] = vs[2]; vd[3] = vs[3];
        }
        __syncthreads();

        // S = Q @ K^T  (per warp: 16 x 64)
        float c[8][4];
        #pragma unroll
        for (int j = 0; j < 8; j++) {
            c[j][0] = c[j][1] = c[j][2] = c[j][3] = 0.0f;
            #pragma unroll
            for (int kt = 0; kt < 4; kt++) {
                uint32_t b[2];
                b[0] = *(const uint32_t*)&Ks[(8 * j + g) * KP + kt * 16 + 2 * tig];
                b[1] = *(const uint32_t*)&Ks[(8 * j + g) * KP + kt * 16 + 2 * tig + 8];
                mma16816(c[j], aq[kt], b);
            }
        }

        // scale + mask + row max
        float mx0 = -1e30f, mx1 = -1e30f;
        #pragma unroll
        for (int j = 0; j < 8; j++) {
            int col = kv0 + 8 * j + 2 * tig;
            float2 mk0 = *(const float2*)(Mg + qrow0 * SS + col);
            float2 mk1 = *(const float2*)(Mg + qrow1 * SS + col);
            c[j][0] = c[j][0] * scale + mk0.x;
            c[j][1] = c[j][1] * scale + mk0.y;
            c[j][2] = c[j][2] * scale + mk1.x;
            c[j][3] = c[j][3] * scale + mk1.y;
            mx0 = fmaxf(mx0, fmaxf(c[j][0], c[j][1]));
            mx1 = fmaxf(mx1, fmaxf(c[j][2], c[j][3]));
        }
        mx0 = fmaxf(mx0, __shfl_xor_sync(0xffffffffu, mx0, 1));
        mx0 = fmaxf(mx0, __shfl_xor_sync(0xffffffffu, mx0, 2));
        mx1 = fmaxf(mx1, __shfl_xor_sync(0xffffffffu, mx1, 1));
        mx1 = fmaxf(mx1, __shfl_xor_sync(0xffffffffu, mx1, 2));

        float mn0 = fmaxf(m_run0, mx0), mn1 = fmaxf(m_run1, mx1);
        float corr0 = __expf(m_run0 - mn0), corr1 = __expf(m_run1 - mn1);
        m_run0 = mn0; m_run1 = mn1;

        float ls0 = 0.0f, ls1 = 0.0f;
        uint32_t p[4][4];
        #pragma unroll
        for (int j = 0; j < 8; j++) {
            float p0 = __expf(c[j][0] - mn0);
            float p1 = __expf(c[j][1] - mn0);
            float p2 = __expf(c[j][2] - mn1);
            float p3 = __expf(c[j][3] - mn1);
            ls0 += p0 + p1;
            ls1 += p2 + p3;
            int kt = j >> 1, hi = (j & 1) * 2;
            p[kt][hi + 0] = packbf(p0, p1);   // A-frag rows g    / cols pair
            p[kt][hi + 1] = packbf(p2, p3);   // A-frag rows g+8
        }
        ls0 += __shfl_xor_sync(0xffffffffu, ls0, 1);
        ls0 += __shfl_xor_sync(0xffffffffu, ls0, 2);
        ls1 += __shfl_xor_sync(0xffffffffu, ls1, 1);
        ls1 += __shfl_xor_sync(0xffffffffu, ls1, 2);
        l_run0 = l_run0 * corr0 + ls0;
        l_run1 = l_run1 * corr1 + ls1;

        #pragma unroll
        for (int jo = 0; jo < 8; jo++) {
            o[jo][0] *= corr0; o[jo][1] *= corr0;
            o[jo][2] *= corr1; o[jo][3] *= corr1;
        }

        // O += P @ V   (B from transposed V tile)
        #pragma unroll
        for (int jo = 0; jo < 8; jo++) {
            #pragma unroll
            for (int kt = 0; kt < 4; kt++) {
                uint32_t b[2];
                b[0] = *(const uint32_t*)&Vs[(8 * jo + g) * KP + kt * 16 + 2 * tig];
                b[1] = *(const uint32_t*)&Vs[(8 * jo + g) * KP + kt * 16 + 2 * tig + 8];
                mma16816(o[jo], p[kt], b);
            }
        }
    }

    // finalize + write ctx bf16 merged-head
    float inv0 = 1.0f / l_run0, inv1 = 1.0f / l_run1;
    #pragma unroll
    for (int jo = 0; jo < 8; jo++) {
        int d = h_ * HDD + 8 * jo + 2 * tig;
        *(uint32_t*)&g_ctxb[(b_ * SS + qrow0) * HH + d] = packbf(o[jo][0] * inv0, o[jo][1] * inv0);
        *(uint32_t*)&g_ctxb[(b_ * SS + qrow1) * HH + d] = packbf(o[jo][2] * inv1, o[jo][3] * inv1);
    }
}

// ---------------------------------------------------------------------------
// Kernel 3: out projection + residual (bf16 mma), resid fp32.
// ---------------------------------------------------------------------------
__global__ __launch_bounds__(128) void proj_kernel(
    const float* __restrict__ X,
    const float* __restrict__ Wo, const float* __restrict__ bo)
{
    __shared__ __nv_bfloat16 As[128 * GP];
    __shared__ __nv_bfloat16 Bs[64 * GP];

    const int t = threadIdx.x;
    const int w = t >> 5, lane = t & 31;
    const int g = lane >> 2, tig = lane & 3;
    const int m0 = blockIdx.y * 128, n0 = blockIdx.x * 64;

    float c[2][8][4];
    #pragma unroll
    for (int mt = 0; mt < 2; mt++)
        #pragma unroll
        for (int j = 0; j < 8; j++)
            #pragma unroll
            for (int i = 0; i < 4; i++) c[mt][j][i] = 0.0f;

    for (int k0 = 0; k0 < HH; k0 += 32) {
        // ctx tile 128x32 bf16 -> As (direct copy)
        #pragma unroll
        for (int i = 0; i < 4; i++) {
            int m = (t >> 2) + 32 * i;
            int k = 8 * (t & 3);
            *(uint4*)&As[m * GP + k] =
                *(const uint4*)&g_ctxb[(m0 + m) * HH + k0 + k];
        }
        // Wo tile 32x64 fp32 -> Bs bf16 transposed [n][k]
        #pragma unroll
        for (int i = 0; i < 8; i++) {
            int idx = 2 * t + 256 * i;
            int k = idx >> 6, n = idx & 63;
            float2 v = *(const float2*)(Wo + (k0 + k) * HH + n0 + n);
            Bs[n * GP + k]       = __float2bfloat16(v.x);
            Bs[(n + 1) * GP + k] = __float2bfloat16(v.y);
        }
        __syncthreads();

        uint32_t a[2][2][4];
        #pragma unroll
        for (int mt = 0; mt < 2; mt++)
            #pragma unroll
            for (int kt = 0; kt < 2; kt++) {
                int r = w * 32 + mt * 16;
                a[mt][kt][0] = *(const uint32_t*)&As[(r + g)     * GP + kt * 16 + 2 * tig];
                a[mt][kt][1] = *(const uint32_t*)&As[(r + g + 8) * GP + kt * 16 + 2 * tig];
                a[mt][kt][2] = *(const uint32_t*)&As[(r + g)     * GP + kt * 16 + 2 * tig + 8];
                a[mt][kt][3] = *(const uint32_t*)&As[(r + g + 8) * GP + kt * 16 + 2 * tig + 8];
            }
        #pragma unroll
        for (int j = 0; j < 8; j++) {
            #pragma unroll
            for (int kt = 0; kt < 2; kt++) {
                uint32_t b[2];
                b[0] = *(const uint32_t*)&Bs[(8 * j + g) * GP + kt * 16 + 2 * tig];
                b[1] = *(const uint32_t*)&Bs[(8 * j + g) * GP + kt * 16 + 2 * tig + 8];
                mma16816(c[0][j], a[0][kt], b);
                mma16816(c[1][j], a[1][kt], b);
            }
        }
        __syncthreads();
    }

    // Epilogue: + bo + X -> resid fp32
    #pragma unroll
    for (int mt = 0; mt < 2; mt++) {
        int r0 = m0 + w * 32 + mt * 16 + g;
        #pragma unroll
        for (int half = 0; half < 2; half++) {
            int m = r0 + half * 8;
            #pragma unroll
            for (int j = 0; j < 8; j++) {
                int n = n0 + 8 * j + 2 * tig;
                float2 xr = *(const float2*)(X + m * HH + n);
                float2 ov;
                ov.x = c[mt][j][half * 2 + 0] + bo[n]     + xr.x;
                ov.y = c[mt][j][half * 2 + 1] + bo[n + 1] + xr.y;
                *(float2*)&g_resid[m * HH + n] = ov;
            }
        }
    }
}

// ---------------------------------------------------------------------------
// Kernel 4: LayerNorm (unchanged, 11us)
// ---------------------------------------------------------------------------
__global__ __launch_bounds__(256) void ln_kernel(
    const float* __restrict__ gamma, const float* __restrict__ beta,
    float* __restrict__ out)
{
    const int lane = threadIdx.x & 31;
    const int warp = threadIdx.x >> 5;
    const int row  = blockIdx.x * 8 + warp;

    const float* r = g_resid + row * HH + lane * 8;
    float4 a  = *(const float4*)(r);
    float4 b4 = *(const float4*)(r + 4);

    float sum = a.x + a.y + a.z + a.w + b4.x + b4.y + b4.z + b4.w;
    #pragma unroll
    for (int off = 16; off; off >>= 1)
        sum += __shfl_xor_sync(0xffffffffu, sum, off);
    float mu = sum * (1.0f / 256.0f);

    float d0 = a.x - mu, d1 = a.y - mu, d2 = a.z - mu, d3 = a.w - mu;
    float d4 = b4.x - mu, d5 = b4.y - mu, d6 = b4.z - mu, d7 = b4.w - mu;
    float vs = d0 * d0 + d1 * d1 + d2 * d2 + d3 * d3
             + d4 * d4 + d5 * d5 + d6 * d6 + d7 * d7;
    #pragma unroll
    for (int off = 16; off; off >>= 1)
        vs += __shfl_xor_sync(0xffffffffu, vs, off);
    float inv = rsqrtf(vs * (1.0f / 256.0f) + 1e-12f);

    float4 g0 = *(const float4*)(gamma + lane * 8);
    float4 g1 = *(const float4*)(gamma + lane * 8 + 4);
    float4 e0 = *(const float4*)(beta + lane * 8);
    float4 e1 = *(const float4*)(beta + lane * 8 + 4);

    float4 o0, o1;
    o0.x = d0 * inv * g0.x + e0.x;
    o0.y = d1 * inv * g0.y + e0.y;
    o0.z = d2 * inv * g0.z + e0.z;
    o0.w = d3 * inv * g0.w + e0.w;
    o1.x = d4 * inv * g1.x + e1.x;
    o1.y = d5 * inv * g1.y + e1.y;
    o1.z = d6 * inv * g1.z + e1.z;
    o1.w = d7 * inv * g1.w + e1.w;

    float* op = out + row * HH + lane * 8;
    *(float4*)(op)     = o0;
    *(float4*)(op + 4) = o1;
}

// ---------------------------------------------------------------------------
extern "C" void kernel_launch(void* const* d_in, const int* in_sizes, int n_in,
                              void* d_out, int out_size)
{
    const float* X     = (const float*)d_in[0];
    const float* mask  = (const float*)d_in[1];
    const float* Wq    = (const float*)d_in[2];
    const float* bq    = (const float*)d_in[3];
    const float* Wk    = (const float*)d_in[4];
    const float* bk    = (const float*)d_in[5];
    const float* Wv    = (const float*)d_in[6];
    const float* bv    = (const float*)d_in[7];
    const float* Wo    = (const float*)d_in[8];
    const float* bo    = (const float*)d_in[9];
    const float* gamma = (const float*)d_in[10];
    const float* beta  = (const float*)d_in[11];
    float* out = (float*)d_out;

    qkv_kernel<<<dim3(HH / 64, MTOT / 128, 3), 128>>>(X, Wq, bq, Wk, bk, Wv, bv);
    attn_kernel<<<dim3(BB * NHH, SS / 64), 128>>>(mask);
    proj_kernel<<<dim3(HH / 64, MTOT / 128), 128>>>(X, Wo, bo);
    ln_kernel<<<MTOT / 8, 256>>>(gamma, beta, out);
}

// round 4
// speedup vs baseline: 4.9244x; 1.0613x over previous
#include <cuda_runtime.h>
#include <cuda_bf16.h>
#include <stdint.h>
#include <math.h>

#define BB   8
#define SS   2048
#define HH   256
#define NHH  4
#define HDD  64
#define MTOT (BB * SS)   // 16384

// ---------------------------------------------------------------------------
// Scratch (__device__ globals only).
// ---------------------------------------------------------------------------
__device__ __align__(128) __nv_bfloat16 g_Qb[32 * SS * HDD];   // [bh][s][d]
__device__ __align__(128) __nv_bfloat16 g_Kb[32 * SS * HDD];   // [bh][s][d]
__device__ __align__(128) __nv_bfloat16 g_Vt[32 * HDD * SS];   // [bh][d][s]
__device__ __align__(128) __nv_bfloat16 g_ctxb[MTOT * HH];     // [m][h*64+d]
__device__ __align__(128) float         g_resid[MTOT * HH];

// ---------------------------------------------------------------------------
// Helpers
// ---------------------------------------------------------------------------
__device__ __forceinline__ uint32_t packbf(float lo, float hi) {
    uint32_t r;
    asm("cvt.rn.bf16x2.f32 %0, %1, %2;" : "=r"(r) : "f"(hi), "f"(lo));
    return r;
}

__device__ __forceinline__ void mma16816(float* c, const uint32_t* a, const uint32_t* b) {
    asm volatile(
        "mma.sync.aligned.m16n8k16.row.col.f32.bf16.bf16.f32 "
        "{%0,%1,%2,%3}, {%4,%5,%6,%7}, {%8,%9}, {%0,%1,%2,%3};\n"
        : "+f"(c[0]), "+f"(c[1]), "+f"(c[2]), "+f"(c[3])
        : "r"(a[0]), "r"(a[1]), "r"(a[2]), "r"(a[3]), "r"(b[0]), "r"(b[1]));
}

__device__ __forceinline__ uint32_t smem_u32(const void* p) {
    uint32_t a;
    asm("{ .reg .u64 t; cvta.to.shared.u64 t, %1; cvt.u32.u64 %0, t; }" : "=r"(a) : "l"(p));
    return a;
}

__device__ __forceinline__ void ldsm4(uint32_t& r0, uint32_t& r1, uint32_t& r2, uint32_t& r3,
                                      uint32_t addr) {
    asm volatile("ldmatrix.sync.aligned.m8n8.x4.shared.b16 {%0,%1,%2,%3}, [%4];"
                 : "=r"(r0), "=r"(r1), "=r"(r2), "=r"(r3) : "r"(addr));
}

__device__ __forceinline__ void cp16(uint32_t dst, const void* src) {
    asm volatile("cp.async.cg.shared.global [%0], [%1], 16;" :: "r"(dst), "l"(src));
}
#define CP_COMMIT() asm volatile("cp.async.commit_group;" ::: "memory")
#define CP_WAIT1()  asm volatile("cp.async.wait_group 1;" ::: "memory")
#define CP_WAIT0()  asm volatile("cp.async.wait_group 0;" ::: "memory")

#define GP 40   // smem pitch for mma.sync GEMM tiles (qkv/proj)

// ---------------------------------------------------------------------------
// Kernel 1: QKV projection (bf16 mma.sync, unchanged from R2)
// ---------------------------------------------------------------------------
__global__ __launch_bounds__(128) void qkv_kernel(
    const float* __restrict__ X,
    const float* __restrict__ Wq, const float* __restrict__ bq,
    const float* __restrict__ Wk, const float* __restrict__ bk,
    const float* __restrict__ Wv, const float* __restrict__ bv)
{
    __shared__ __nv_bfloat16 As[128 * GP];
    __shared__ __nv_bfloat16 Bs[64 * GP];

    const int z = blockIdx.z;
    const float* W;  const float* bias;
    if (z == 0)      { W = Wq; bias = bq; }
    else if (z == 1) { W = Wk; bias = bk; }
    else             { W = Wv; bias = bv; }

    const int t = threadIdx.x;
    const int w = t >> 5, lane = t & 31;
    const int g = lane >> 2, tig = lane & 3;
    const int m0 = blockIdx.y * 128, n0 = blockIdx.x * 64;

    float c[2][8][4];
    #pragma unroll
    for (int mt = 0; mt < 2; mt++)
        #pragma unroll
        for (int j = 0; j < 8; j++)
            #pragma unroll
            for (int i = 0; i < 4; i++) c[mt][j][i] = 0.0f;

    for (int k0 = 0; k0 < HH; k0 += 32) {
        #pragma unroll
        for (int i = 0; i < 8; i++) {
            int m = (t >> 3) + 16 * i;
            int k = 4 * (t & 7);
            float4 v = *(const float4*)(X + (m0 + m) * HH + k0 + k);
            uint2 p;
            p.x = packbf(v.x, v.y);
            p.y = packbf(v.z, v.w);
            *(uint2*)&As[m * GP + k] = p;
        }
        #pragma unroll
        for (int i = 0; i < 8; i++) {
            int idx = 2 * t + 256 * i;
            int k = idx >> 6, n = idx & 63;
            float2 v = *(const float2*)(W + (k0 + k) * HH + n0 + n);
            Bs[n * GP + k]       = __float2bfloat16(v.x);
            Bs[(n + 1) * GP + k] = __float2bfloat16(v.y);
        }
        __syncthreads();

        uint32_t a[2][2][4];
        #pragma unroll
        for (int mt = 0; mt < 2; mt++)
            #pragma unroll
            for (int kt = 0; kt < 2; kt++) {
                int r = w * 32 + mt * 16;
                a[mt][kt][0] = *(const uint32_t*)&As[(r + g)     * GP + kt * 16 + 2 * tig];
                a[mt][kt][1] = *(const uint32_t*)&As[(r + g + 8) * GP + kt * 16 + 2 * tig];
                a[mt][kt][2] = *(const uint32_t*)&As[(r + g)     * GP + kt * 16 + 2 * tig + 8];
                a[mt][kt][3] = *(const uint32_t*)&As[(r + g + 8) * GP + kt * 16 + 2 * tig + 8];
            }
        #pragma unroll
        for (int j = 0; j < 8; j++) {
            #pragma unroll
            for (int kt = 0; kt < 2; kt++) {
                uint32_t b[2];
                b[0] = *(const uint32_t*)&Bs[(8 * j + g) * GP + kt * 16 + 2 * tig];
                b[1] = *(const uint32_t*)&Bs[(8 * j + g) * GP + kt * 16 + 2 * tig + 8];
                mma16816(c[0][j], a[0][kt], b);
                mma16816(c[1][j], a[1][kt], b);
            }
        }
        __syncthreads();
    }

    const int head = blockIdx.x;
    #pragma unroll
    for (int mt = 0; mt < 2; mt++) {
        int r0 = m0 + w * 32 + mt * 16 + g;
        #pragma unroll
        for (int half = 0; half < 2; half++) {
            int m  = r0 + half * 8;
            int b_ = m >> 11;
            int s_ = m & (SS - 1);
            int bh = b_ * NHH + head;
            #pragma unroll
            for (int j = 0; j < 8; j++) {
                int d = 8 * j + 2 * tig;
                float v0 = c[mt][j][half * 2 + 0] + bias[n0 + d];
                float v1 = c[mt][j][half * 2 + 1] + bias[n0 + d + 1];
                if (z == 0) {
                    *(uint32_t*)&g_Qb[(bh * SS + s_) * HDD + d] = packbf(v0, v1);
                } else if (z == 1) {
                    *(uint32_t*)&g_Kb[(bh * SS + s_) * HDD + d] = packbf(v0, v1);
                } else {
                    g_Vt[(bh * HDD + d)     * SS + s_] = __float2bfloat16(v0);
                    g_Vt[(bh * HDD + d + 1) * SS + s_] = __float2bfloat16(v1);
                }
            }
        }
    }
}

// ---------------------------------------------------------------------------
// Kernel 2: flash attention, bf16 mma.sync, BQ=128 (32 rows/warp), BK=64.
// ldmatrix B-frags, cp.async double-buffered K/V, no-max softmax.
// Smem tiles: rows of 128B, XOR-swizzled (term = (row&7)*16).
// ---------------------------------------------------------------------------
#define NIT 32   // SS / 64

struct __align__(1024) AttnSmem {
    __nv_bfloat16 K[2][64 * 64];
    __nv_bfloat16 V[2][64 * 64];
};

__global__ __launch_bounds__(128) void attn_kernel(const float* __restrict__ mask)
{
    __shared__ AttnSmem sm;

    const int t = threadIdx.x;
    const int w = t >> 5, lane = t & 31;
    const int g = lane >> 2, tig = lane & 3;
    const int bh = blockIdx.x;
    const int qb = blockIdx.y;
    const int b_ = bh >> 2;
    const int h_ = bh & 3;

    const uint32_t kbase[2] = { smem_u32(&sm.K[0][0]), smem_u32(&sm.K[1][0]) };
    const uint32_t vbase[2] = { smem_u32(&sm.V[0][0]), smem_u32(&sm.V[1][0]) };

    const __nv_bfloat16* Qg = g_Qb + (size_t)bh * SS * HDD;
    const __nv_bfloat16* Kg = g_Kb + (size_t)bh * SS * HDD;
    const __nv_bfloat16* Vg = g_Vt + (size_t)bh * HDD * SS;
    const float* Mb = mask + (size_t)b_ * SS * SS;

    // cp.async loader chunk indices (per thread: 4 chunks K + 4 chunks V)
    // chunk c = t + 128*jc : row = c>>3 (0..63), seg = c&7 (16B within row)
    // swizzled dst offset = row*128 + ((seg*16) ^ ((row&7)*16))
    int ld_row[4], ld_dst[4];
    #pragma unroll
    for (int jc = 0; jc < 4; jc++) {
        int c = t + 128 * jc;
        int row = c >> 3, seg = c & 7;
        ld_row[jc] = row;
        ld_dst[jc] = row * 128 + ((seg * 16) ^ ((row & 7) * 16));
    }

    // ldmatrix per-thread addressing
    // t0-7:  rows n0+(t&7),   k bytes 0..15   -> r0 (b0 of n-block 0)
    // t8-15: rows n0+(t&7),   k bytes 16..31  -> r1 (b1 of n-block 0)
    // t16-23:rows n0+8+(t&7), k bytes 0..15   -> r2 (b0 of n-block 1)
    // t24-31:rows n0+8+(t&7), k bytes 16..31  -> r3 (b1 of n-block 1)
    const int lrow = (lane & 7) | ((lane & 16) >> 1);
    const int lkb  = (lane & 8) ? 16 : 0;
    const int lxor = (lrow & 7) * 16;
    const int lbase = lrow * 128;         // + jj*2048 + ((kt*32+lkb)^lxor)

    // Q A-fragments (2 m-tiles of 16 rows), resident all iterations
    const int qrow[2] = { qb * 128 + w * 32 + g, qb * 128 + w * 32 + 16 + g };
    uint32_t aq[2][4][4];
    #pragma unroll
    for (int mt = 0; mt < 2; mt++) {
        const __nv_bfloat16* r0 = Qg + (size_t)qrow[mt] * HDD;
        const __nv_bfloat16* r1 = r0 + 8 * HDD;
        #pragma unroll
        for (int kt = 0; kt < 4; kt++) {
            aq[mt][kt][0] = *(const uint32_t*)(r0 + kt * 16 + 2 * tig);
            aq[mt][kt][1] = *(const uint32_t*)(r1 + kt * 16 + 2 * tig);
            aq[mt][kt][2] = *(const uint32_t*)(r0 + kt * 16 + 2 * tig + 8);
            aq[mt][kt][3] = *(const uint32_t*)(r1 + kt * 16 + 2 * tig + 8);
        }
    }

    // issue K/V tiles for iter 0 and 1
    #pragma unroll
    for (int it = 0; it < 2; it++) {
        const char* Ksrc = (const char*)(Kg + it * 64 * HDD);
        const char* Vsrc = (const char*)Vg;
        #pragma unroll
        for (int jc = 0; jc < 4; jc++) {
            int row = ld_row[jc];
            int off = ld_dst[jc] & ~127;           // row*128
            int seg16 = (t & 7) * 16;              // source byte within row
            cp16(kbase[it] + ld_dst[jc], Ksrc + off + seg16);
            cp16(vbase[it] + ld_dst[jc], Vsrc + (size_t)row * (SS * 2) + it * 128 + seg16);
        }
        CP_COMMIT();
    }

    float o[2][8][4];
    #pragma unroll
    for (int mt = 0; mt < 2; mt++)
        #pragma unroll
        for (int j = 0; j < 8; j++)
            #pragma unroll
            for (int i = 0; i < 4; i++) o[mt][j][i] = 0.0f;
    float lacc[2][2] = {{0.0f, 0.0f}, {0.0f, 0.0f}};

    for (int i = 0; i < NIT; i++) {
        const int buf = i & 1;
        if (i < NIT - 1) { CP_WAIT1(); } else { CP_WAIT0(); }
        __syncthreads();

        // ---- S = Q @ K^T : c[2][8][4], shared B-frags via ldmatrix ----
        float c[2][8][4];
        #pragma unroll
        for (int mt = 0; mt < 2; mt++)
            #pragma unroll
            for (int j = 0; j < 8; j++)
                #pragma unroll
                for (int q = 0; q < 4; q++) c[mt][j][q] = 0.0f;

        #pragma unroll
        for (int jj = 0; jj < 4; jj++) {
            #pragma unroll
            for (int kt = 0; kt < 4; kt++) {
                uint32_t r0, r1, r2, r3;
                ldsm4(r0, r1, r2, r3,
                      kbase[buf] + jj * 2048 + lbase + ((kt * 32 + lkb) ^ lxor));
                uint32_t blo[2] = { r0, r1 }, bhi[2] = { r2, r3 };
                mma16816(c[0][2 * jj],     aq[0][kt], blo);
                mma16816(c[0][2 * jj + 1], aq[0][kt], bhi);
                mma16816(c[1][2 * jj],     aq[1][kt], blo);
                mma16816(c[1][2 * jj + 1], aq[1][kt], bhi);
            }
        }

        // ---- softmax (no max subtraction) + pack P as PV A-frags ----
        uint32_t pa[2][4][4];
        #pragma unroll
        for (int mt = 0; mt < 2; mt++) {
            const float* mp0 = Mb + (size_t)qrow[mt] * SS + i * 64 + 2 * tig;
            const float* mp1 = mp0 + 8 * SS;
            float2 mk0[8], mk1[8];
            #pragma unroll
            for (int j = 0; j < 8; j++) {
                mk0[j] = *(const float2*)(mp0 + 8 * j);
                mk1[j] = *(const float2*)(mp1 + 8 * j);
            }
            #pragma unroll
            for (int j = 0; j < 8; j++) {
                float p0 = __expf(fmaf(c[mt][j][0], 0.125f, mk0[j].x));
                float p1 = __expf(fmaf(c[mt][j][1], 0.125f, mk0[j].y));
                float p2 = __expf(fmaf(c[mt][j][2], 0.125f, mk1[j].x));
                float p3 = __expf(fmaf(c[mt][j][3], 0.125f, mk1[j].y));
                lacc[mt][0] += p0 + p1;
                lacc[mt][1] += p2 + p3;
                int kt = j >> 1, hi = (j & 1) * 2;
                pa[mt][kt][hi + 0] = packbf(p0, p1);
                pa[mt][kt][hi + 1] = packbf(p2, p3);
            }
        }

        // ---- O += P @ V (V tile is [d][kv], same ldmatrix pattern) ----
        #pragma unroll
        for (int jj = 0; jj < 4; jj++) {
            #pragma unroll
            for (int kt = 0; kt < 4; kt++) {
                uint32_t r0, r1, r2, r3;
                ldsm4(r0, r1, r2, r3,
                      vbase[buf] + jj * 2048 + lbase + ((kt * 32 + lkb) ^ lxor));
                uint32_t blo[2] = { r0, r1 }, bhi[2] = { r2, r3 };
                mma16816(o[0][2 * jj],     pa[0][kt], blo);
                mma16816(o[0][2 * jj + 1], pa[0][kt], bhi);
                mma16816(o[1][2 * jj],     pa[1][kt], blo);
                mma16816(o[1][2 * jj + 1], pa[1][kt], bhi);
            }
        }

        __syncthreads();   // everyone done reading buf before it is overwritten

        if (i + 2 < NIT) {
            const int it = i + 2;
            const char* Ksrc = (const char*)(Kg + (size_t)it * 64 * HDD);
            const char* Vsrc = (const char*)Vg;
            #pragma unroll
            for (int jc = 0; jc < 4; jc++) {
                int row = ld_row[jc];
                int off = ld_dst[jc] & ~127;
                int seg16 = (t & 7) * 16;
                cp16(kbase[buf] + ld_dst[jc], Ksrc + off + seg16);
                cp16(vbase[buf] + ld_dst[jc], Vsrc + (size_t)row * (SS * 2) + it * 128 + seg16);
            }
            CP_COMMIT();
        }
    }

    // ---- final: reduce l across the 4 lanes of each row group, write ctx ----
    #pragma unroll
    for (int mt = 0; mt < 2; mt++)
        #pragma unroll
        for (int h = 0; h < 2; h++) {
            float v = lacc[mt][h];
            v += __shfl_xor_sync(0xffffffffu, v, 1);
            v += __shfl_xor_sync(0xffffffffu, v, 2);
            lacc[mt][h] = 1.0f / v;
        }

    #pragma unroll
    for (int mt = 0; mt < 2; mt++) {
        __nv_bfloat16* c0 = g_ctxb + ((size_t)b_ * SS + qrow[mt]) * HH + h_ * HDD;
        __nv_bfloat16* c1 = c0 + 8 * HH;
        #pragma unroll
        for (int j = 0; j < 8; j++) {
            int d = 8 * j + 2 * tig;
            *(uint32_t*)(c0 + d) = packbf(o[mt][j][0] * lacc[mt][0],
                                          o[mt][j][1] * lacc[mt][0]);
            *(uint32_t*)(c1 + d) = packbf(o[mt][j][2] * lacc[mt][1],
                                          o[mt][j][3] * lacc[mt][1]);
        }
    }
}

// ---------------------------------------------------------------------------
// Kernel 3: out projection + residual (bf16 mma.sync, unchanged)
// ---------------------------------------------------------------------------
__global__ __launch_bounds__(128) void proj_kernel(
    const float* __restrict__ X,
    const float* __restrict__ Wo, const float* __restrict__ bo)
{
    __shared__ __nv_bfloat16 As[128 * GP];
    __shared__ __nv_bfloat16 Bs[64 * GP];

    const int t = threadIdx.x;
    const int w = t >> 5, lane = t & 31;
    const int g = lane >> 2, tig = lane & 3;
    const int m0 = blockIdx.y * 128, n0 = blockIdx.x * 64;

    float c[2][8][4];
    #pragma unroll
    for (int mt = 0; mt < 2; mt++)
        #pragma unroll
        for (int j = 0; j < 8; j++)
            #pragma unroll
            for (int i = 0; i < 4; i++) c[mt][j][i] = 0.0f;

    for (int k0 = 0; k0 < HH; k0 += 32) {
        #pragma unroll
        for (int i = 0; i < 4; i++) {
            int m = (t >> 2) + 32 * i;
            int k = 8 * (t & 3);
            *(uint4*)&As[m * GP + k] =
                *(const uint4*)&g_ctxb[(m0 + m) * HH + k0 + k];
        }
        #pragma unroll
        for (int i = 0; i < 8; i++) {
            int idx = 2 * t + 256 * i;
            int k = idx >> 6, n = idx & 63;
            float2 v = *(const float2*)(Wo + (k0 + k) * HH + n0 + n);
            Bs[n * GP + k]       = __float2bfloat16(v.x);
            Bs[(n + 1) * GP + k] = __float2bfloat16(v.y);
        }
        __syncthreads();

        uint32_t a[2][2][4];
        #pragma unroll
        for (int mt = 0; mt < 2; mt++)
            #pragma unroll
            for (int kt = 0; kt < 2; kt++) {
                int r = w * 32 + mt * 16;
                a[mt][kt][0] = *(const uint32_t*)&As[(r + g)     * GP + kt * 16 + 2 * tig];
                a[mt][kt][1] = *(const uint32_t*)&As[(r + g + 8) * GP + kt * 16 + 2 * tig];
                a[mt][kt][2] = *(const uint32_t*)&As[(r + g)     * GP + kt * 16 + 2 * tig + 8];
                a[mt][kt][3] = *(const uint32_t*)&As[(r + g + 8) * GP + kt * 16 + 2 * tig + 8];
            }
        #pragma unroll
        for (int j = 0; j < 8; j++) {
            #pragma unroll
            for (int kt = 0; kt < 2; kt++) {
                uint32_t b[2];
                b[0] = *(const uint32_t*)&Bs[(8 * j + g) * GP + kt * 16 + 2 * tig];
                b[1] = *(const uint32_t*)&Bs[(8 * j + g) * GP + kt * 16 + 2 * tig + 8];
                mma16816(c[0][j], a[0][kt], b);
                mma16816(c[1][j], a[1][kt], b);
            }
        }
        __syncthreads();
    }

    #pragma unroll
    for (int mt = 0; mt < 2; mt++) {
        int r0 = m0 + w * 32 + mt * 16 + g;
        #pragma unroll
        for (int half = 0; half < 2; half++) {
            int m = r0 + half * 8;
            #pragma unroll
            for (int j = 0; j < 8; j++) {
                int n = n0 + 8 * j + 2 * tig;
                float2 xr = *(const float2*)(X + m * HH + n);
                float2 ov;
                ov.x = c[mt][j][half * 2 + 0] + bo[n]     + xr.x;
                ov.y = c[mt][j][half * 2 + 1] + bo[n + 1] + xr.y;
                *(float2*)&g_resid[m * HH + n] = ov;
            }
        }
    }
}

// ---------------------------------------------------------------------------
// Kernel 4: LayerNorm (unchanged)
// ---------------------------------------------------------------------------
__global__ __launch_bounds__(256) void ln_kernel(
    const float* __restrict__ gamma, const float* __restrict__ beta,
    float* __restrict__ out)
{
    const int lane = threadIdx.x & 31;
    const int warp = threadIdx.x >> 5;
    const int row  = blockIdx.x * 8 + warp;

    const float* r = g_resid + row * HH + lane * 8;
    float4 a  = *(const float4*)(r);
    float4 b4 = *(const float4*)(r + 4);

    float sum = a.x + a.y + a.z + a.w + b4.x + b4.y + b4.z + b4.w;
    #pragma unroll
    for (int off = 16; off; off >>= 1)
        sum += __shfl_xor_sync(0xffffffffu, sum, off);
    float mu = sum * (1.0f / 256.0f);

    float d0 = a.x - mu, d1 = a.y - mu, d2 = a.z - mu, d3 = a.w - mu;
    float d4 = b4.x - mu, d5 = b4.y - mu, d6 = b4.z - mu, d7 = b4.w - mu;
    float vs = d0 * d0 + d1 * d1 + d2 * d2 + d3 * d3
             + d4 * d4 + d5 * d5 + d6 * d6 + d7 * d7;
    #pragma unroll
    for (int off = 16; off; off >>= 1)
        vs += __shfl_xor_sync(0xffffffffu, vs, off);
    float inv = rsqrtf(vs * (1.0f / 256.0f) + 1e-12f);

    float4 g0 = *(const float4*)(gamma + lane * 8);
    float4 g1 = *(const float4*)(gamma + lane * 8 + 4);
    float4 e0 = *(const float4*)(beta + lane * 8);
    float4 e1 = *(const float4*)(beta + lane * 8 + 4);

    float4 o0, o1;
    o0.x = d0 * inv * g0.x + e0.x;
    o0.y = d1 * inv * g0.y + e0.y;
    o0.z = d2 * inv * g0.z + e0.z;
    o0.w = d3 * inv * g0.w + e0.w;
    o1.x = d4 * inv * g1.x + e1.x;
    o1.y = d5 * inv * g1.y + e1.y;
    o1.z = d6 * inv * g1.z + e1.z;
    o1.w = d7 * inv * g1.w + e1.w;

    float* op = out + row * HH + lane * 8;
    *(float4*)(op)     = o0;
    *(float4*)(op + 4) = o1;
}

// ---------------------------------------------------------------------------
extern "C" void kernel_launch(void* const* d_in, const int* in_sizes, int n_in,
                              void* d_out, int out_size)
{
    const float* X     = (const float*)d_in[0];
    const float* mask  = (const float*)d_in[1];
    const float* Wq    = (const float*)d_in[2];
    const float* bq    = (const float*)d_in[3];
    const float* Wk    = (const float*)d_in[4];
    const float* bk    = (const float*)d_in[5];
    const float* Wv    = (const float*)d_in[6];
    const float* bv    = (const float*)d_in[7];
    const float* Wo    = (const float*)d_in[8];
    const float* bo    = (const float*)d_in[9];
    const float* gamma = (const float*)d_in[10];
    const float* beta  = (const float*)d_in[11];
    float* out = (float*)d_out;

    qkv_kernel<<<dim3(HH / 64, MTOT / 128, 3), 128>>>(X, Wq, bq, Wk, bk, Wv, bv);
    attn_kernel<<<dim3(BB * NHH, SS / 128), 128>>>(mask);
    proj_kernel<<<dim3(HH / 64, MTOT / 128), 128>>>(X, Wo, bo);
    ln_kernel<<<MTOT / 8, 256>>>(gamma, beta, out);
}